// round 11
// baseline (speedup 1.0000x reference)
#include <cuda_runtime.h>

#define BATCH 16
#define P 2048
#define KNN 16
#define NPTS (BATCH*P)

// ---------------- scratch (device globals; no allocation allowed) ----------
__device__ int    g_idx[NPTS*KNN];          // global neighbor indices
__device__ float4 g_ppf4[NPTS*KNN];         // ppf features per (i,k)
__device__ float4 g_x1v[NPTS*8];            // x1 (32 floats / point)
__device__ int    g_gmax[BATCH*128];        // global max (float bits, >=0)

// ---------------- helpers ---------------------------------------------------
__device__ __forceinline__ float4 f4max(float4 a, float4 b){
    return make_float4(fmaxf(a.x,b.x), fmaxf(a.y,b.y), fmaxf(a.z,b.z), fmaxf(a.w,b.w));
}
__device__ __forceinline__ float4 f4relu(float4 a){
    return make_float4(fmaxf(a.x,0.f), fmaxf(a.y,0.f), fmaxf(a.z,0.f), fmaxf(a.w,0.f));
}
__device__ __forceinline__ float4 f4fma(float m, float4 w, float4 a){
    a.x = fmaf(m,w.x,a.x); a.y = fmaf(m,w.y,a.y);
    a.z = fmaf(m,w.z,a.z); a.w = fmaf(m,w.w,a.w);
    return a;
}
__device__ __forceinline__ float warpmax8(float v){
    v = fmaxf(v, __shfl_xor_sync(0xffffffffu, v, 4));
    v = fmaxf(v, __shfl_xor_sync(0xffffffffu, v, 8));
    v = fmaxf(v, __shfl_xor_sync(0xffffffffu, v, 16));
    return v;
}
// angle(v1, v2) = arctan2(||v1 x v2||, v1.v2).
// Degenerate case ||cross||==0 (the self-neighbor: pseudo = (+0,+0,+0)):
// the reference's jnp.sum is an XLA reduce with init +0, and IEEE (+0)+(-0)=+0,
// so its dot is NEVER -0 -> arctan2(+0, +0) = 0 for every self-pair.
// A local fmaf/add chain CAN yield -0 (all-negative normals, ~1/8 of points),
// and atan2f(+0,-0)=pi — the source of the frozen 6.646e-2 error across all
// prior rounds. Ordered compare d < 0 treats -0 as non-negative: returns 0
// for +-0, pi only for a genuinely negative dot (exact antipodal, measure 0).
__device__ __forceinline__ float angle3(float ax,float ay,float az,
                                        float bx,float by,float bz){
    float cx = ay*bz - az*by;
    float cy = az*bx - ax*bz;
    float cz = ax*by - ay*bx;
    float c2 = fmaf(cx,cx, fmaf(cy,cy, cz*cz));
    float d  = fmaf(ax,bx, fmaf(ay,by, az*bz));
    if (c2 == 0.0f)
        return (d < 0.0f) ? 3.14159265358979323846f : 0.0f;
    return atan2f(sqrtf(c2), d);
}

// ---------------- kernel 0: zero the global-max accumulator ----------------
__global__ void zero_kernel(){
    int t = blockIdx.x*blockDim.x + threadIdx.x;
    if (t < BATCH*128) g_gmax[t] = 0;
}

// ---------------- kernel 1: flat brute-force KNN (top-16 smallest d2) ------
__global__ __launch_bounds__(256) void knn_kernel(const float* __restrict__ pos){
    int gi   = blockIdx.x*256 + threadIdx.x;
    int base = (gi >> 11) * P;
    float px = pos[gi*3+0], py = pos[gi*3+1], pz = pos[gi*3+2];

    float bd[KNN];
    int   bi[KNN];
    #pragma unroll
    for (int s=0;s<KNN;s++){ bd[s] = 3.4e38f; bi[s] = 0; }
    float worst = 3.4e38f; int wslot = 0;

    #pragma unroll 1
    for (int j=0; j<P; j++){
        const float* pj = pos + (base + j)*3;
        float dx = __fadd_rn(pj[0], -px);
        float dy = __fadd_rn(pj[1], -py);
        float dz = __fadd_rn(pj[2], -pz);
        float d2 = __fadd_rn(__fadd_rn(__fmul_rn(dx,dx), __fmul_rn(dy,dy)),
                             __fmul_rn(dz,dz));
        if (d2 < worst){                            // strict <: earliest index wins ties
            #pragma unroll
            for (int s=0;s<KNN;s++){                // predicated replace (static idx)
                bool r = (s == wslot);
                bd[s] = r ? d2 : bd[s];
                bi[s] = r ? j  : bi[s];
            }
            worst = -1.f; wslot = 0;
            #pragma unroll
            for (int s=0;s<KNN;s++){ if (bd[s] > worst){ worst = bd[s]; wslot = s; } }
        }
    }
    #pragma unroll
    for (int s=0;s<KNN;s++) g_idx[gi*KNN+s] = base + bi[s];
}

// ---------------- kernel 2: PPF + MLP1 (4->16->32, max over K), scalar -----
__global__ __launch_bounds__(128) void ppf_mlp1_kernel(
    const float* __restrict__ pos, const float* __restrict__ nor,
    const float* __restrict__ w1a, const float* __restrict__ b1a,
    const float* __restrict__ w1b, const float* __restrict__ b1b){

    __shared__ float sw1a[64];      // [i<4][o<16] row-major
    __shared__ float sb1a[16];
    __shared__ float sw1b[512];     // [i<16][o<32] row-major
    __shared__ float sb1b[32];
    int tid = threadIdx.x;
    if (tid < 64)  sw1a[tid] = w1a[tid];
    if (tid < 16)  sb1a[tid] = b1a[tid];
    for (int u=tid; u<512; u+=128) sw1b[u] = w1b[u];
    if (tid < 32)  sb1b[tid] = b1b[tid];
    __syncthreads();

    int gi = blockIdx.x*128 + tid;
    float px = pos[gi*3+0], py = pos[gi*3+1], pz = pos[gi*3+2];
    float nx = nor[gi*3+0], ny = nor[gi*3+1], nz = nor[gi*3+2];

    float xm[32];
    #pragma unroll
    for (int o=0;o<32;o++) xm[o] = -3.4e38f;

    #pragma unroll 1
    for (int k=0; k<KNN; k++){
        int j  = g_idx[gi*KNN+k];
        float qx = pos[j*3+0], qy = pos[j*3+1], qz = pos[j*3+2];
        float mx = nor[j*3+0], my = nor[j*3+1], mz = nor[j*3+2];
        float dx = qx-px, dy = qy-py, dz = qz-pz;
        float p0 = sqrtf(fmaf(dx,dx, fmaf(dy,dy, dz*dz)));
        float p1 = angle3(nx,ny,nz, dx,dy,dz);
        float p2 = angle3(mx,my,mz, dx,dy,dz);
        float p3 = angle3(nx,ny,nz, mx,my,mz);
        g_ppf4[gi*KNN+k] = make_float4(p0,p1,p2,p3);

        float h1[16];
        #pragma unroll
        for (int o=0;o<16;o++){
            float a = sb1a[o];
            a = fmaf(p0, sw1a[0*16+o], a);
            a = fmaf(p1, sw1a[1*16+o], a);
            a = fmaf(p2, sw1a[2*16+o], a);
            a = fmaf(p3, sw1a[3*16+o], a);
            h1[o] = fmaxf(a, 0.f);
        }
        #pragma unroll
        for (int o=0;o<32;o++){
            float a = sb1b[o];
            #pragma unroll
            for (int i=0;i<16;i++) a = fmaf(h1[i], sw1b[i*32+o], a);
            xm[o] = fmaxf(xm[o], a);
        }
    }
    #pragma unroll
    for (int o=0;o<32;o++)
        ((float*)g_x1v)[gi*32+o] = fmaxf(xm[o], 0.f);
}

// ---------------- kernel 3: MLP2 (36->64->128, max over K, global max) -----
// R7 float4 version (bit-equivalent to the R8 naive reimplementation, faster).
// 4 threads/point; thread q computes hidden slots r4*4+q, exchanges via the
// padded smem row, owns interleaved output chunks o4*4+q.
__global__ __launch_bounds__(128) void mlp2_kernel(
    const float* __restrict__ w2a, const float* __restrict__ b2a,
    const float* __restrict__ w2b, const float* __restrict__ b2b){

    extern __shared__ float4 sm[];
    float4* s_w2a = sm;            // 576:  [i<36][oc<16]  (64 hidden)
    float4* s_w2b = sm + 576;      // 2048: [i<64][oc<32]  (128 outs)
    float4* s_b2a = sm + 2624;     // 16
    float4* s_b2b = sm + 2640;     // 32
    float4* s_h   = sm + 2672;     // 32 points * 17 (stride-17 pad: bank-free)

    for (int u=threadIdx.x; u<36*16; u+=128) s_w2a[u] = ((const float4*)w2a)[u];
    for (int u=threadIdx.x; u<64*32; u+=128) s_w2b[u] = ((const float4*)w2b)[u];
    if (threadIdx.x < 16) s_b2a[threadIdx.x] = ((const float4*)b2a)[threadIdx.x];
    if (threadIdx.x >= 32 && threadIdx.x < 64)
        s_b2b[threadIdx.x-32] = ((const float4*)b2b)[threadIdx.x-32];
    __syncthreads();

    const int tid = threadIdx.x;
    const int q   = tid & 3;
    const int lp  = tid >> 2;           // local point 0..31
    const int pt  = blockIdx.x*32 + lp;
    const float4* Wa = s_w2a + q;       // Wa[i*16 + r4*4] -> hidden chunk r4*4+q
    const float4* Wb = s_w2b + q;       // Wb[i*32 + o4*4] -> output chunk o4*4+q
    float4* hrow = s_h + lp*17;

    float4 xm0 = make_float4(-3.4e38f,-3.4e38f,-3.4e38f,-3.4e38f);
    float4 xm1 = xm0, xm2 = xm0, xm3 = xm0, xm4 = xm0, xm5 = xm0, xm6 = xm0, xm7 = xm0;

    #pragma unroll 1
    for (int k=0; k<KNN; k++){
        int j = g_idx[pt*KNN+k];
        const float4* xj = &g_x1v[j*8];
        float4 v0 = xj[0], v1 = xj[1], v2 = xj[2], v3 = xj[3];
        float4 v4 = xj[4], v5 = xj[5], v6 = xj[6], v7 = xj[7];
        float4 v8 = g_ppf4[pt*KNN+k];

        // layer 2a: 36 -> 64, this thread computes hidden chunks r4*4+q
        float4 h0 = s_b2a[0*4+q], h1 = s_b2a[1*4+q];
        float4 h2 = s_b2a[2*4+q], h3 = s_b2a[3*4+q];
        #define L1(mm, i) { h0=f4fma(mm,Wa[(i)*16+0],h0);  h1=f4fma(mm,Wa[(i)*16+4],h1); \
                            h2=f4fma(mm,Wa[(i)*16+8],h2);  h3=f4fma(mm,Wa[(i)*16+12],h3); }
        #define L1V(vv, b) L1(vv.x,(b)) L1(vv.y,(b)+1) L1(vv.z,(b)+2) L1(vv.w,(b)+3)
        L1V(v0,0) L1V(v1,4) L1V(v2,8) L1V(v3,12) L1V(v4,16)
        L1V(v5,20) L1V(v6,24) L1V(v7,28) L1V(v8,32)
        #undef L1V
        #undef L1
        h0 = f4relu(h0); h1 = f4relu(h1); h2 = f4relu(h2); h3 = f4relu(h3);

        // exchange hidden via shared (protect previous iteration's reads first)
        __syncwarp();
        hrow[0*4+q] = h0; hrow[1*4+q] = h1; hrow[2*4+q] = h2; hrow[3*4+q] = h3;
        __syncwarp();

        // layer 2b: 64 -> 128, this thread owns output chunks o4*4+q
        float4 a0 = s_b2b[0*4+q], a1 = s_b2b[1*4+q], a2 = s_b2b[2*4+q], a3 = s_b2b[3*4+q];
        float4 a4 = s_b2b[4*4+q], a5 = s_b2b[5*4+q], a6 = s_b2b[6*4+q], a7 = s_b2b[7*4+q];
        #define L2ONE(mm, i) { a0=f4fma(mm,Wb[(i)*32+0],a0);  a1=f4fma(mm,Wb[(i)*32+4],a1); \
                               a2=f4fma(mm,Wb[(i)*32+8],a2);  a3=f4fma(mm,Wb[(i)*32+12],a3); \
                               a4=f4fma(mm,Wb[(i)*32+16],a4); a5=f4fma(mm,Wb[(i)*32+20],a5); \
                               a6=f4fma(mm,Wb[(i)*32+24],a6); a7=f4fma(mm,Wb[(i)*32+28],a7); }
        #pragma unroll
        for (int i4=0; i4<16; i4++){
            float4 hv = hrow[i4];            // channels 4*i4+c == w2b rows 4*i4+c
            L2ONE(hv.x, i4*4+0)
            L2ONE(hv.y, i4*4+1)
            L2ONE(hv.z, i4*4+2)
            L2ONE(hv.w, i4*4+3)
        }
        #undef L2ONE

        xm0 = f4max(xm0, a0); xm1 = f4max(xm1, a1);
        xm2 = f4max(xm2, a2); xm3 = f4max(xm3, a3);
        xm4 = f4max(xm4, a4); xm5 = f4max(xm5, a5);
        xm6 = f4max(xm6, a6); xm7 = f4max(xm7, a7);
    }

    #define RED(vv) { vv = f4relu(vv); vv.x = warpmax8(vv.x); vv.y = warpmax8(vv.y); \
                      vv.z = warpmax8(vv.z); vv.w = warpmax8(vv.w); }
    RED(xm0) RED(xm1) RED(xm2) RED(xm3) RED(xm4) RED(xm5) RED(xm6) RED(xm7)
    #undef RED

    if ((tid & 31) < 4){                  // one lane per quarter
        int b = pt >> 11;
        #define ATO(vv, o4) { int base = b*128 + (((o4)*4+q)<<2); \
            atomicMax(&g_gmax[base+0], __float_as_int(vv.x)); \
            atomicMax(&g_gmax[base+1], __float_as_int(vv.y)); \
            atomicMax(&g_gmax[base+2], __float_as_int(vv.z)); \
            atomicMax(&g_gmax[base+3], __float_as_int(vv.w)); }
        ATO(xm0,0) ATO(xm1,1) ATO(xm2,2) ATO(xm3,3)
        ATO(xm4,4) ATO(xm5,5) ATO(xm6,6) ATO(xm7,7)
        #undef ATO
    }
}

// ---------------- kernel 4: final linear 128 -> 10 --------------------------
__global__ void final_kernel(const float* __restrict__ wc,
                             const float* __restrict__ bc,
                             float* __restrict__ out){
    int t = blockIdx.x*blockDim.x + threadIdx.x;
    if (t < BATCH*10){
        int b = t/10, o = t - b*10;
        float acc = bc[o];
        #pragma unroll 16
        for (int i=0; i<128; i++)
            acc = fmaf(__int_as_float(g_gmax[b*128+i]), wc[i*10+o], acc);
        out[t] = acc;
    }
}

// ---------------- launch -----------------------------------------------------
extern "C" void kernel_launch(void* const* d_in, const int* in_sizes, int n_in,
                              void* d_out, int out_size){
    const float* pos = (const float*)d_in[0];
    const float* nor = (const float*)d_in[1];
    // d_in[2] = batch (redundant: contiguous blocks of P)
    const float* w1a = (const float*)d_in[3];
    const float* b1a = (const float*)d_in[4];
    const float* w1b = (const float*)d_in[5];
    const float* b1b = (const float*)d_in[6];
    const float* w2a = (const float*)d_in[7];
    const float* b2a = (const float*)d_in[8];
    const float* w2b = (const float*)d_in[9];
    const float* b2b = (const float*)d_in[10];
    const float* wc  = (const float*)d_in[11];
    const float* bc  = (const float*)d_in[12];

    const int mlp2_smem = 3216 * 16;   // 51456 B dynamic shared
    cudaFuncSetAttribute(mlp2_kernel, cudaFuncAttributeMaxDynamicSharedMemorySize, mlp2_smem);

    zero_kernel<<<2, 1024>>>();
    knn_kernel<<<NPTS/256, 256>>>(pos);
    ppf_mlp1_kernel<<<NPTS/128, 128>>>(pos, nor, w1a, b1a, w1b, b1b);
    mlp2_kernel<<<NPTS/32, 128, mlp2_smem>>>(w2a, b2a, w2b, b2b);
    final_kernel<<<1, 192>>>(wc, bc, (float*)d_out);
}

// round 12
// speedup vs baseline: 1.6161x; 1.6161x over previous
#include <cuda_runtime.h>

#define BATCH 16
#define P 2048
#define KNN 16
#define NPTS (BATCH*P)

// ---------------- scratch (device globals; no allocation allowed) ----------
__device__ int    g_idx[NPTS*KNN];          // global neighbor indices
__device__ float4 g_ppf4[NPTS*KNN];         // ppf features per (i,k)
__device__ float4 g_x1v[NPTS*8];            // x1 (32 floats / point)
__device__ int    g_gmax[BATCH*128];        // global max (float bits, >=0)

// ---------------- helpers ---------------------------------------------------
__device__ __forceinline__ float4 f4max(float4 a, float4 b){
    return make_float4(fmaxf(a.x,b.x), fmaxf(a.y,b.y), fmaxf(a.z,b.z), fmaxf(a.w,b.w));
}
__device__ __forceinline__ float4 f4relu(float4 a){
    return make_float4(fmaxf(a.x,0.f), fmaxf(a.y,0.f), fmaxf(a.z,0.f), fmaxf(a.w,0.f));
}
__device__ __forceinline__ float4 f4fma(float m, float4 w, float4 a){
    a.x = fmaf(m,w.x,a.x); a.y = fmaf(m,w.y,a.y);
    a.z = fmaf(m,w.z,a.z); a.w = fmaf(m,w.w,a.w);
    return a;
}
// reduce over the 4 point-groups of a warp (lane bits [4:3]), preserving q (bits [2:0])
__device__ __forceinline__ float warpmax4g(float v){
    v = fmaxf(v, __shfl_xor_sync(0xffffffffu, v, 8));
    v = fmaxf(v, __shfl_xor_sync(0xffffffffu, v, 16));
    return v;
}
// angle(v1, v2) = arctan2(||v1 x v2||, v1.v2).
// Degenerate ||cross||==0 (self-neighbor, pseudo=(+0,+0,+0)): the reference's
// jnp.sum (XLA reduce, init +0; IEEE (+0)+(-0)=+0) NEVER yields -0, so its
// arctan2(+0, +-0) is always 0. Ordered d < 0 treats -0 as non-negative.
__device__ __forceinline__ float angle3(float ax,float ay,float az,
                                        float bx,float by,float bz){
    float cx = ay*bz - az*by;
    float cy = az*bx - ax*bz;
    float cz = ax*by - ay*bx;
    float c2 = fmaf(cx,cx, fmaf(cy,cy, cz*cz));
    float d  = fmaf(ax,bx, fmaf(ay,by, az*bz));
    if (c2 == 0.0f)
        return (d < 0.0f) ? 3.14159265358979323846f : 0.0f;
    return atan2f(sqrtf(c2), d);
}

// ---------------- kernel 0: zero the global-max accumulator ----------------
__global__ void zero_kernel(){
    int t = blockIdx.x*blockDim.x + threadIdx.x;
    if (t < BATCH*128) g_gmax[t] = 0;
}

// ---------------- kernel 1: flat brute-force KNN (top-16 smallest d2) ------
__global__ __launch_bounds__(256) void knn_kernel(const float* __restrict__ pos){
    int gi   = blockIdx.x*256 + threadIdx.x;
    int base = (gi >> 11) * P;
    float px = pos[gi*3+0], py = pos[gi*3+1], pz = pos[gi*3+2];

    float bd[KNN];
    int   bi[KNN];
    #pragma unroll
    for (int s=0;s<KNN;s++){ bd[s] = 3.4e38f; bi[s] = 0; }
    float worst = 3.4e38f; int wslot = 0;

    #pragma unroll 1
    for (int j=0; j<P; j++){
        const float* pj = pos + (base + j)*3;
        float dx = __fadd_rn(pj[0], -px);
        float dy = __fadd_rn(pj[1], -py);
        float dz = __fadd_rn(pj[2], -pz);
        float d2 = __fadd_rn(__fadd_rn(__fmul_rn(dx,dx), __fmul_rn(dy,dy)),
                             __fmul_rn(dz,dz));
        if (d2 < worst){                            // strict <: earliest index wins ties
            #pragma unroll
            for (int s=0;s<KNN;s++){                // predicated replace (static idx)
                bool r = (s == wslot);
                bd[s] = r ? d2 : bd[s];
                bi[s] = r ? j  : bi[s];
            }
            worst = -1.f; wslot = 0;
            #pragma unroll
            for (int s=0;s<KNN;s++){ if (bd[s] > worst){ worst = bd[s]; wslot = s; } }
        }
    }
    #pragma unroll
    for (int s=0;s<KNN;s++) g_idx[gi*KNN+s] = base + bi[s];
}

// ---------------- kernel 2: PPF + MLP1 (4->16->32, max over K), scalar -----
__global__ __launch_bounds__(128) void ppf_mlp1_kernel(
    const float* __restrict__ pos, const float* __restrict__ nor,
    const float* __restrict__ w1a, const float* __restrict__ b1a,
    const float* __restrict__ w1b, const float* __restrict__ b1b){

    __shared__ float sw1a[64];      // [i<4][o<16] row-major
    __shared__ float sb1a[16];
    __shared__ float sw1b[512];     // [i<16][o<32] row-major
    __shared__ float sb1b[32];
    int tid = threadIdx.x;
    if (tid < 64)  sw1a[tid] = w1a[tid];
    if (tid < 16)  sb1a[tid] = b1a[tid];
    for (int u=tid; u<512; u+=128) sw1b[u] = w1b[u];
    if (tid < 32)  sb1b[tid] = b1b[tid];
    __syncthreads();

    int gi = blockIdx.x*128 + tid;
    float px = pos[gi*3+0], py = pos[gi*3+1], pz = pos[gi*3+2];
    float nx = nor[gi*3+0], ny = nor[gi*3+1], nz = nor[gi*3+2];

    float xm[32];
    #pragma unroll
    for (int o=0;o<32;o++) xm[o] = -3.4e38f;

    #pragma unroll 1
    for (int k=0; k<KNN; k++){
        int j  = g_idx[gi*KNN+k];
        float qx = pos[j*3+0], qy = pos[j*3+1], qz = pos[j*3+2];
        float mx = nor[j*3+0], my = nor[j*3+1], mz = nor[j*3+2];
        float dx = qx-px, dy = qy-py, dz = qz-pz;
        float p0 = sqrtf(fmaf(dx,dx, fmaf(dy,dy, dz*dz)));
        float p1 = angle3(nx,ny,nz, dx,dy,dz);
        float p2 = angle3(mx,my,mz, dx,dy,dz);
        float p3 = angle3(nx,ny,nz, mx,my,mz);
        g_ppf4[gi*KNN+k] = make_float4(p0,p1,p2,p3);

        float h1[16];
        #pragma unroll
        for (int o=0;o<16;o++){
            float a = sb1a[o];
            a = fmaf(p0, sw1a[0*16+o], a);
            a = fmaf(p1, sw1a[1*16+o], a);
            a = fmaf(p2, sw1a[2*16+o], a);
            a = fmaf(p3, sw1a[3*16+o], a);
            h1[o] = fmaxf(a, 0.f);
        }
        #pragma unroll
        for (int o=0;o<32;o++){
            float a = sb1b[o];
            #pragma unroll
            for (int i=0;i<16;i++) a = fmaf(h1[i], sw1b[i*32+o], a);
            xm[o] = fmaxf(xm[o], a);
        }
    }
    #pragma unroll
    for (int o=0;o<32;o++)
        ((float*)g_x1v)[gi*32+o] = fmaxf(xm[o], 0.f);
}

// ---------------- kernel 3: MLP2 (36->64->128, max over K, global max) -----
// Register-tiled for smem-wavefront reuse: 8 threads per point, 4 points per
// thread. Thread q (=tid&7) owns hidden chunks {q, q+8} and output chunks
// {q, q+8, q+16, q+24} (stride 8 -> lanes 0-7 read 8 distinct contiguous
// float4 = 128B per phase, conflict-free full wavefronts). Each weight
// LDS.128 feeds 16 FMAs (4 comps x 4 points) vs 4 before: ~6.7x less
// smem traffic per point — the R11 ncu bottleneck (L1 93.5%).
__global__ __launch_bounds__(128) void mlp2_kernel(
    const float* __restrict__ w2a, const float* __restrict__ b2a,
    const float* __restrict__ w2b, const float* __restrict__ b2b){

    extern __shared__ float4 sm[];
    float4* s_w2a = sm;            // 576:  [i<36][c<16]  (64 hidden)
    float4* s_w2b = sm + 576;      // 2048: [i<64][c<32]  (128 outs)
    float4* s_b2a = sm + 2624;     // 16
    float4* s_b2b = sm + 2640;     // 32
    float4* s_h   = sm + 2672;     // 64 points * 17 (stride-17 pad)

    for (int u=threadIdx.x; u<36*16; u+=128) s_w2a[u] = ((const float4*)w2a)[u];
    for (int u=threadIdx.x; u<64*32; u+=128) s_w2b[u] = ((const float4*)w2b)[u];
    if (threadIdx.x < 16) s_b2a[threadIdx.x] = ((const float4*)b2a)[threadIdx.x];
    if (threadIdx.x >= 32 && threadIdx.x < 64)
        s_b2b[threadIdx.x-32] = ((const float4*)b2b)[threadIdx.x-32];
    __syncthreads();

    const int tid = threadIdx.x;
    const int q   = tid & 7;               // chunk owner id
    const int G   = tid >> 3;              // point group 0..15
    const int pA  = blockIdx.x*64 + G;     // 4 points, stride 16
    const int pB  = pA + 16, pC = pA + 32, pD = pA + 48;
    float4* hrA = s_h + (G+ 0)*17;
    float4* hrB = s_h + (G+16)*17;
    float4* hrC = s_h + (G+32)*17;
    float4* hrD = s_h + (G+48)*17;

    float4 ninf = make_float4(-3.4e38f,-3.4e38f,-3.4e38f,-3.4e38f);
    float4 xmA0=ninf, xmA1=ninf, xmA2=ninf, xmA3=ninf;
    float4 xmB0=ninf, xmB1=ninf, xmB2=ninf, xmB3=ninf;
    float4 xmC0=ninf, xmC1=ninf, xmC2=ninf, xmC3=ninf;
    float4 xmD0=ninf, xmD1=ninf, xmD2=ninf, xmD3=ninf;

    #pragma unroll 1
    for (int k=0; k<KNN; k++){
        int jA = g_idx[pA*KNN+k], jB = g_idx[pB*KNN+k];
        int jC = g_idx[pC*KNN+k], jD = g_idx[pD*KNN+k];
        const float4* xA = g_x1v + jA*8;
        const float4* xB = g_x1v + jB*8;
        const float4* xC = g_x1v + jC*8;
        const float4* xD = g_x1v + jD*8;

        // ---- layer 2a: 36 -> 64; this thread: hidden chunks q, q+8 --------
        float4 hA0 = s_b2a[q], hA1 = s_b2a[q+8];
        float4 hB0 = hA0, hB1 = hA1, hC0 = hA0, hC1 = hA1, hD0 = hA0, hD1 = hA1;
        #define STEP2A(mA_, mB_, mC_, mD_, i) { \
            float4 w0_ = s_w2a[(i)*16 + q]; float4 w1_ = s_w2a[(i)*16 + 8 + q]; \
            hA0 = f4fma(mA_, w0_, hA0); hB0 = f4fma(mB_, w0_, hB0); \
            hC0 = f4fma(mC_, w0_, hC0); hD0 = f4fma(mD_, w0_, hD0); \
            hA1 = f4fma(mA_, w1_, hA1); hB1 = f4fma(mB_, w1_, hB1); \
            hC1 = f4fma(mC_, w1_, hC1); hD1 = f4fma(mD_, w1_, hD1); }
        #pragma unroll
        for (int i4=0; i4<8; i4++){
            float4 vA = xA[i4], vB = xB[i4], vC = xC[i4], vD = xD[i4];
            STEP2A(vA.x, vB.x, vC.x, vD.x, i4*4+0)
            STEP2A(vA.y, vB.y, vC.y, vD.y, i4*4+1)
            STEP2A(vA.z, vB.z, vC.z, vD.z, i4*4+2)
            STEP2A(vA.w, vB.w, vC.w, vD.w, i4*4+3)
        }
        {
            float4 vA = g_ppf4[pA*KNN+k], vB = g_ppf4[pB*KNN+k];
            float4 vC = g_ppf4[pC*KNN+k], vD = g_ppf4[pD*KNN+k];
            STEP2A(vA.x, vB.x, vC.x, vD.x, 32)
            STEP2A(vA.y, vB.y, vC.y, vD.y, 33)
            STEP2A(vA.z, vB.z, vC.z, vD.z, 34)
            STEP2A(vA.w, vB.w, vC.w, vD.w, 35)
        }
        #undef STEP2A
        hA0 = f4relu(hA0); hA1 = f4relu(hA1);
        hB0 = f4relu(hB0); hB1 = f4relu(hB1);
        hC0 = f4relu(hC0); hC1 = f4relu(hC1);
        hD0 = f4relu(hD0); hD1 = f4relu(hD1);

        // ---- exchange hidden within the 8-thread group --------------------
        __syncwarp();
        hrA[q] = hA0; hrA[8+q] = hA1;
        hrB[q] = hB0; hrB[8+q] = hB1;
        hrC[q] = hC0; hrC[8+q] = hC1;
        hrD[q] = hD0; hrD[8+q] = hD1;
        __syncwarp();

        // ---- layer 2b: 64 -> 128; this thread: out chunks q,q+8,q+16,q+24 -
        float4 aA0 = s_b2b[q], aA1 = s_b2b[q+8], aA2 = s_b2b[q+16], aA3 = s_b2b[q+24];
        float4 aB0 = aA0, aB1 = aA1, aB2 = aA2, aB3 = aA3;
        float4 aC0 = aA0, aC1 = aA1, aC2 = aA2, aC3 = aA3;
        float4 aD0 = aA0, aD1 = aA1, aD2 = aA2, aD3 = aA3;
        #define STEP2B(sA_, sB_, sC_, sD_, i) { \
            float4 w_; \
            w_ = s_w2b[(i)*32 + q]; \
            aA0 = f4fma(sA_, w_, aA0); aB0 = f4fma(sB_, w_, aB0); \
            aC0 = f4fma(sC_, w_, aC0); aD0 = f4fma(sD_, w_, aD0); \
            w_ = s_w2b[(i)*32 + 8 + q]; \
            aA1 = f4fma(sA_, w_, aA1); aB1 = f4fma(sB_, w_, aB1); \
            aC1 = f4fma(sC_, w_, aC1); aD1 = f4fma(sD_, w_, aD1); \
            w_ = s_w2b[(i)*32 + 16 + q]; \
            aA2 = f4fma(sA_, w_, aA2); aB2 = f4fma(sB_, w_, aB2); \
            aC2 = f4fma(sC_, w_, aC2); aD2 = f4fma(sD_, w_, aD2); \
            w_ = s_w2b[(i)*32 + 24 + q]; \
            aA3 = f4fma(sA_, w_, aA3); aB3 = f4fma(sB_, w_, aB3); \
            aC3 = f4fma(sC_, w_, aC3); aD3 = f4fma(sD_, w_, aD3); }
        #pragma unroll 4
        for (int i4=0; i4<16; i4++){
            float4 hvA = hrA[i4], hvB = hrB[i4], hvC = hrC[i4], hvD = hrD[i4];
            STEP2B(hvA.x, hvB.x, hvC.x, hvD.x, i4*4+0)
            STEP2B(hvA.y, hvB.y, hvC.y, hvD.y, i4*4+1)
            STEP2B(hvA.z, hvB.z, hvC.z, hvD.z, i4*4+2)
            STEP2B(hvA.w, hvB.w, hvC.w, hvD.w, i4*4+3)
        }
        #undef STEP2B

        xmA0 = f4max(xmA0, aA0); xmA1 = f4max(xmA1, aA1);
        xmA2 = f4max(xmA2, aA2); xmA3 = f4max(xmA3, aA3);
        xmB0 = f4max(xmB0, aB0); xmB1 = f4max(xmB1, aB1);
        xmB2 = f4max(xmB2, aB2); xmB3 = f4max(xmB3, aB3);
        xmC0 = f4max(xmC0, aC0); xmC1 = f4max(xmC1, aC1);
        xmC2 = f4max(xmC2, aC2); xmC3 = f4max(xmC3, aC3);
        xmD0 = f4max(xmD0, aD0); xmD1 = f4max(xmD1, aD1);
        xmD2 = f4max(xmD2, aD2); xmD3 = f4max(xmD3, aD3);
    }

    // merge 4 points, relu, reduce over the warp's 4 groups, atomic
    float4 r0 = f4relu(f4max(f4max(xmA0,xmB0), f4max(xmC0,xmD0)));
    float4 r1 = f4relu(f4max(f4max(xmA1,xmB1), f4max(xmC1,xmD1)));
    float4 r2 = f4relu(f4max(f4max(xmA2,xmB2), f4max(xmC2,xmD2)));
    float4 r3 = f4relu(f4max(f4max(xmA3,xmB3), f4max(xmC3,xmD3)));
    #define RED(vv) { vv.x = warpmax4g(vv.x); vv.y = warpmax4g(vv.y); \
                      vv.z = warpmax4g(vv.z); vv.w = warpmax4g(vv.w); }
    RED(r0) RED(r1) RED(r2) RED(r3)
    #undef RED

    if ((tid & 31) < 8){                   // one lane per chunk owner q
        int b = blockIdx.x >> 5;           // 32 blocks per batch (64 pts/block)
        #define ATO(vv, m) { int base = b*128 + ((q + 8*(m))<<2); \
            atomicMax(&g_gmax[base+0], __float_as_int(vv.x)); \
            atomicMax(&g_gmax[base+1], __float_as_int(vv.y)); \
            atomicMax(&g_gmax[base+2], __float_as_int(vv.z)); \
            atomicMax(&g_gmax[base+3], __float_as_int(vv.w)); }
        ATO(r0,0) ATO(r1,1) ATO(r2,2) ATO(r3,3)
        #undef ATO
    }
}

// ---------------- kernel 4: final linear 128 -> 10 --------------------------
__global__ void final_kernel(const float* __restrict__ wc,
                             const float* __restrict__ bc,
                             float* __restrict__ out){
    int t = blockIdx.x*blockDim.x + threadIdx.x;
    if (t < BATCH*10){
        int b = t/10, o = t - b*10;
        float acc = bc[o];
        #pragma unroll 16
        for (int i=0; i<128; i++)
            acc = fmaf(__int_as_float(g_gmax[b*128+i]), wc[i*10+o], acc);
        out[t] = acc;
    }
}

// ---------------- launch -----------------------------------------------------
extern "C" void kernel_launch(void* const* d_in, const int* in_sizes, int n_in,
                              void* d_out, int out_size){
    const float* pos = (const float*)d_in[0];
    const float* nor = (const float*)d_in[1];
    // d_in[2] = batch (redundant: contiguous blocks of P)
    const float* w1a = (const float*)d_in[3];
    const float* b1a = (const float*)d_in[4];
    const float* w1b = (const float*)d_in[5];
    const float* b1b = (const float*)d_in[6];
    const float* w2a = (const float*)d_in[7];
    const float* b2a = (const float*)d_in[8];
    const float* w2b = (const float*)d_in[9];
    const float* b2b = (const float*)d_in[10];
    const float* wc  = (const float*)d_in[11];
    const float* bc  = (const float*)d_in[12];

    const int mlp2_smem = 3760 * 16;   // 60160 B dynamic shared
    cudaFuncSetAttribute(mlp2_kernel, cudaFuncAttributeMaxDynamicSharedMemorySize, mlp2_smem);

    zero_kernel<<<2, 1024>>>();
    knn_kernel<<<NPTS/256, 256>>>(pos);
    ppf_mlp1_kernel<<<NPTS/128, 128>>>(pos, nor, w1a, b1a, w1b, b1b);
    mlp2_kernel<<<NPTS/64, 128, mlp2_smem>>>(w2a, b2a, w2b, b2b);
    final_kernel<<<1, 192>>>(wc, bc, (float*)d_out);
}